// round 1
// baseline (speedup 1.0000x reference)
#include <cuda_runtime.h>
#include <cstdint>

#define NUM_GRAPHS 16384
#define EMB_DIM 128

// Read index i of the graph-id array, which may be int32 or int64 on disk.
__device__ __forceinline__ int idx_at(const void* __restrict__ b, int i, bool is64) {
    if (is64) return (int)(((const long long* __restrict__)b)[i]);
    return ((const int* __restrict__)b)[i];
}

// Detect element width: indices are sorted ids in [0, 16384). Viewed as int32,
// position n-1 (odd) is the high word of an int64 element => 0, whereas for
// int32 layout it is the last (largest) id => nonzero.
__device__ __forceinline__ bool detect_is64(const void* __restrict__ b, int n) {
    return ((const int* __restrict__)b)[n - 1] == 0;
}

__device__ __forceinline__ int lower_bound_idx(const void* __restrict__ b, int n,
                                               int key, bool is64) {
    int lo = 0, hi = n;
    while (lo < hi) {
        int mid = (lo + hi) >> 1;
        if (idx_at(b, mid, is64) < key) lo = mid + 1;
        else hi = mid;
    }
    return lo;
}

__global__ __launch_bounds__(128, 8)
void fragnet_pool_kernel(const float* __restrict__ x_atoms,
                         const float* __restrict__ x_frags,
                         const void* __restrict__ batch,
                         const void* __restrict__ frag_batch,
                         float* __restrict__ out,
                         int n_atoms, int n_frags) {
    const int g    = blockIdx.x;
    const int warp = threadIdx.x >> 5;
    const int lane = threadIdx.x & 31;

    __shared__ int bounds[4];        // [atoms_start, atoms_end, frags_start, frags_end]
    __shared__ float4 sh[4][32];     // cross-warp partials (one row of 128 floats as float4/lane)

    // 4 concurrent binary searches (one per thread of warp 0, SIMD within the warp).
    if (threadIdx.x < 4) {
        const bool frags = (threadIdx.x >= 2);
        const void* b = frags ? frag_batch : batch;
        const int   n = frags ? n_frags : n_atoms;
        const bool  is64 = detect_is64(b, n);
        const int   key  = g + (threadIdx.x & 1);   // start: key=g, end: key=g+1
        bounds[threadIdx.x] = lower_bound_idx(b, n, key, is64);
    }
    __syncthreads();

    #pragma unroll
    for (int half = 0; half < 2; half++) {
        const float* __restrict__ x = (half == 0) ? x_atoms : x_frags;
        const int start = bounds[half * 2];
        const int end   = bounds[half * 2 + 1];

        float4 acc = make_float4(0.f, 0.f, 0.f, 0.f);
        // Each warp takes rows start+warp, start+warp+4, ... ; each lane one float4
        // => one full 512B row per warp-iteration, perfectly coalesced LDG.128.
        int r = start + warp;
        // Unroll-by-2 for MLP (independent loads in flight).
        for (; r + 4 < end; r += 8) {
            float4 v0 = reinterpret_cast<const float4*>(x + (size_t)r * EMB_DIM)[lane];
            float4 v1 = reinterpret_cast<const float4*>(x + (size_t)(r + 4) * EMB_DIM)[lane];
            acc.x += v0.x; acc.y += v0.y; acc.z += v0.z; acc.w += v0.w;
            acc.x += v1.x; acc.y += v1.y; acc.z += v1.z; acc.w += v1.w;
        }
        if (r < end) {
            float4 v = reinterpret_cast<const float4*>(x + (size_t)r * EMB_DIM)[lane];
            acc.x += v.x; acc.y += v.y; acc.z += v.z; acc.w += v.w;
        }

        sh[warp][lane] = acc;
        __syncthreads();
        if (warp == 0) {
            float4 a0 = sh[0][lane], a1 = sh[1][lane], a2 = sh[2][lane], a3 = sh[3][lane];
            float4 s = make_float4(a0.x + a1.x + a2.x + a3.x,
                                   a0.y + a1.y + a2.y + a3.y,
                                   a0.z + a1.z + a2.z + a3.z,
                                   a0.w + a1.w + a2.w + a3.w);
            // out[g, half*128 + lane*4 .. +3]
            reinterpret_cast<float4*>(out + (size_t)g * (2 * EMB_DIM) + half * EMB_DIM)[lane] = s;
        }
        __syncthreads();
    }
}

extern "C" void kernel_launch(void* const* d_in, const int* in_sizes, int n_in,
                              void* d_out, int out_size) {
    const float* x_atoms    = (const float*)d_in[0];
    const float* x_frags    = (const float*)d_in[1];
    const void*  batch      = d_in[2];
    const void*  frag_batch = d_in[3];
    float* out = (float*)d_out;

    const int n_atoms = in_sizes[2];   // element count of batch  (2,000,000)
    const int n_frags = in_sizes[3];   // element count of frag_batch (1,000,000)

    fragnet_pool_kernel<<<NUM_GRAPHS, 128>>>(x_atoms, x_frags, batch, frag_batch,
                                             out, n_atoms, n_frags);
}

// round 2
// speedup vs baseline: 1.0711x; 1.0711x over previous
#include <cuda_runtime.h>
#include <cstdint>

#define NUM_GRAPHS 16384
#define EMB_DIM 128

// Precomputed segment boundaries (lower_bound of each graph id), built by the
// prologue kernel. offs[g] = first row index with id >= g; offs[NUM_GRAPHS] = n.
__device__ int g_offs_atoms[NUM_GRAPHS + 1];
__device__ int g_offs_frags[NUM_GRAPHS + 1];

// Read index i of the graph-id array, which may be int32 or int64 on disk.
__device__ __forceinline__ int idx_at(const void* __restrict__ b, int i, bool is64) {
    if (is64) return (int)(((const long long* __restrict__)b)[i]);
    return ((const int* __restrict__)b)[i];
}

// Detect element width: ids are sorted in [0, 16384). Viewed as int32, position
// n-1 (odd) is the high word of an int64 element => 0; for int32 layout it is
// the last (largest) id => nonzero.
__device__ __forceinline__ bool detect_is64(const void* __restrict__ b, int n) {
    return ((const int* __restrict__)b)[n - 1] == 0;
}

// Linear scan: for every position where the sorted id changes, write the
// boundary for all ids in the gap. Total writes across the grid = NUM_GRAPHS+1.
__global__ void build_offsets_kernel(const void* __restrict__ b, int n,
                                     int* __restrict__ offs) {
    const bool is64 = detect_is64(b, n);
    const int stride = gridDim.x * blockDim.x;
    for (int i = blockIdx.x * blockDim.x + threadIdx.x; i < n; i += stride) {
        const int cur  = idx_at(b, i, is64);
        const int prev = (i == 0) ? -1 : idx_at(b, i - 1, is64);
        for (int id = prev + 1; id <= cur; ++id) offs[id] = i;
        if (i == n - 1) {
            for (int id = cur + 1; id <= NUM_GRAPHS; ++id) offs[id] = n;
        }
    }
}

__global__ __launch_bounds__(128, 8)
void fragnet_pool_kernel(const float* __restrict__ x_atoms,
                         const float* __restrict__ x_frags,
                         float* __restrict__ out) {
    const int g    = blockIdx.x;
    const int warp = threadIdx.x >> 5;
    const int lane = threadIdx.x & 31;

    __shared__ int bounds[4];        // [a_start, a_end, f_start, f_end]
    __shared__ float4 sh[4][32];     // cross-warp partials

    if (threadIdx.x < 4) {
        const int* offs = (threadIdx.x >= 2) ? g_offs_frags : g_offs_atoms;
        bounds[threadIdx.x] = offs[g + (threadIdx.x & 1)];
    }
    __syncthreads();

    #pragma unroll
    for (int half = 0; half < 2; half++) {
        const float* __restrict__ x = (half == 0) ? x_atoms : x_frags;
        const int start = bounds[half * 2];
        const int end   = bounds[half * 2 + 1];

        float4 acc0 = make_float4(0.f, 0.f, 0.f, 0.f);
        float4 acc1 = make_float4(0.f, 0.f, 0.f, 0.f);

        // Each warp strides rows by 4; each lane one float4 => one full 512B
        // row per warp-iteration (coalesced LDG.128). Unroll 4 for MLP.
        int r = start + warp;
        for (; r + 12 < end; r += 16) {
            float4 v0 = reinterpret_cast<const float4*>(x + (size_t)r * EMB_DIM)[lane];
            float4 v1 = reinterpret_cast<const float4*>(x + (size_t)(r + 4) * EMB_DIM)[lane];
            float4 v2 = reinterpret_cast<const float4*>(x + (size_t)(r + 8) * EMB_DIM)[lane];
            float4 v3 = reinterpret_cast<const float4*>(x + (size_t)(r + 12) * EMB_DIM)[lane];
            acc0.x += v0.x; acc0.y += v0.y; acc0.z += v0.z; acc0.w += v0.w;
            acc1.x += v1.x; acc1.y += v1.y; acc1.z += v1.z; acc1.w += v1.w;
            acc0.x += v2.x; acc0.y += v2.y; acc0.z += v2.z; acc0.w += v2.w;
            acc1.x += v3.x; acc1.y += v3.y; acc1.z += v3.z; acc1.w += v3.w;
        }
        for (; r < end; r += 4) {
            float4 v = reinterpret_cast<const float4*>(x + (size_t)r * EMB_DIM)[lane];
            acc0.x += v.x; acc0.y += v.y; acc0.z += v.z; acc0.w += v.w;
        }
        acc0.x += acc1.x; acc0.y += acc1.y; acc0.z += acc1.z; acc0.w += acc1.w;

        sh[warp][lane] = acc0;
        __syncthreads();
        if (warp == 0) {
            float4 a0 = sh[0][lane], a1 = sh[1][lane], a2 = sh[2][lane], a3 = sh[3][lane];
            float4 s = make_float4(a0.x + a1.x + a2.x + a3.x,
                                   a0.y + a1.y + a2.y + a3.y,
                                   a0.z + a1.z + a2.z + a3.z,
                                   a0.w + a1.w + a2.w + a3.w);
            reinterpret_cast<float4*>(out + (size_t)g * (2 * EMB_DIM) + half * EMB_DIM)[lane] = s;
        }
        __syncthreads();
    }
}

extern "C" void kernel_launch(void* const* d_in, const int* in_sizes, int n_in,
                              void* d_out, int out_size) {
    const float* x_atoms    = (const float*)d_in[0];
    const float* x_frags    = (const float*)d_in[1];
    const void*  batch      = d_in[2];
    const void*  frag_batch = d_in[3];
    float* out = (float*)d_out;

    const int n_atoms = in_sizes[2];
    const int n_frags = in_sizes[3];

    int* offs_atoms = nullptr;
    int* offs_frags = nullptr;
    cudaGetSymbolAddress((void**)&offs_atoms, g_offs_atoms);
    cudaGetSymbolAddress((void**)&offs_frags, g_offs_frags);

    const int T = 256;
    build_offsets_kernel<<<(n_atoms + T - 1) / T, T>>>(batch, n_atoms, offs_atoms);
    build_offsets_kernel<<<(n_frags + T - 1) / T, T>>>(frag_batch, n_frags, offs_frags);
    fragnet_pool_kernel<<<NUM_GRAPHS, 128>>>(x_atoms, x_frags, out);
}

// round 3
// speedup vs baseline: 1.0887x; 1.0164x over previous
#include <cuda_runtime.h>
#include <cstdint>

#define NUM_GRAPHS 16384
#define EMB_DIM 128

// Precomputed segment boundaries (lower_bound of each graph id).
// offs[g] = first row with id >= g; offs[NUM_GRAPHS] = n.
__device__ int g_offs_atoms[NUM_GRAPHS + 1];
__device__ int g_offs_frags[NUM_GRAPHS + 1];

__device__ __forceinline__ int idx_at(const void* __restrict__ b, int i, bool is64) {
    if (is64) return (int)(((const long long* __restrict__)b)[i]);
    return ((const int* __restrict__)b)[i];
}

// Ids are sorted in [0, 16384). Viewed as int32, position n-1 (odd) is the high
// word of an int64 element => 0; for int32 layout it's the last id => nonzero.
__device__ __forceinline__ bool detect_is64(const void* __restrict__ b, int n) {
    return ((const int* __restrict__)b)[n - 1] == 0;
}

// Fused, vectorized prologue: one launch covers BOTH index arrays. Each thread
// handles an 8-element chunk via 16B vector loads; boundary writes total
// 2*(NUM_GRAPHS+1) across the whole grid.
__global__ void build_offsets_fused(const void* __restrict__ a, int na, int* __restrict__ offsA,
                                    const void* __restrict__ f, int nf, int* __restrict__ offsF) {
    const int chunksA = (na + 7) >> 3;
    const int chunksF = (nf + 7) >> 3;
    const int total   = chunksA + chunksF;
    const int stride  = gridDim.x * blockDim.x;

    for (int c = blockIdx.x * blockDim.x + threadIdx.x; c < total; c += stride) {
        const bool isF = (c >= chunksA);
        const void* __restrict__ b = isF ? f : a;
        const int n = isF ? nf : na;
        int* __restrict__ offs = isF ? offsF : offsA;
        const int base = (isF ? (c - chunksA) : c) << 3;
        const bool is64 = detect_is64(b, n);

        int ids[8];
        if (base + 8 <= n) {
            if (is64) {
                const ulonglong2* p = (const ulonglong2*)((const long long*)b + base);
                ulonglong2 v0 = p[0], v1 = p[1], v2 = p[2], v3 = p[3];
                ids[0] = (int)v0.x; ids[1] = (int)v0.y;
                ids[2] = (int)v1.x; ids[3] = (int)v1.y;
                ids[4] = (int)v2.x; ids[5] = (int)v2.y;
                ids[6] = (int)v3.x; ids[7] = (int)v3.y;
            } else {
                const int4* p = (const int4*)((const int*)b + base);
                int4 v0 = p[0], v1 = p[1];
                ids[0] = v0.x; ids[1] = v0.y; ids[2] = v0.z; ids[3] = v0.w;
                ids[4] = v1.x; ids[5] = v1.y; ids[6] = v1.z; ids[7] = v1.w;
            }
            int prev = (base == 0) ? -1 : idx_at(b, base - 1, is64);
            #pragma unroll
            for (int j = 0; j < 8; j++) {
                const int cur = ids[j];
                if (cur != prev) {
                    for (int id = prev + 1; id <= cur; ++id) offs[id] = base + j;
                    prev = cur;
                }
            }
            if (base + 8 == n) {
                for (int id = ids[7] + 1; id <= NUM_GRAPHS; ++id) offs[id] = n;
            }
        } else {
            // scalar tail (only if n not divisible by 8)
            int prev = (base == 0) ? -1 : idx_at(b, base - 1, is64);
            for (int i = base; i < n; i++) {
                const int cur = idx_at(b, i, is64);
                for (int id = prev + 1; id <= cur; ++id) offs[id] = i;
                prev = cur;
                if (i == n - 1) {
                    for (int id = cur + 1; id <= NUM_GRAPHS; ++id) offs[id] = n;
                }
            }
        }
    }
}

__device__ __forceinline__ void acc_add(float4& a, const float4& v) {
    a.x += v.x; a.y += v.y; a.z += v.z; a.w += v.w;
}

__global__ __launch_bounds__(128, 8)
void fragnet_pool_kernel(const float* __restrict__ x_atoms,
                         const float* __restrict__ x_frags,
                         float* __restrict__ out) {
    const int g    = blockIdx.x;
    const int warp = threadIdx.x >> 5;
    const int lane = threadIdx.x & 31;

    __shared__ int bounds[4];          // [a_start, a_end, f_start, f_end]
    __shared__ float4 shA[4][32];
    __shared__ float4 shF[4][32];

    if (threadIdx.x < 4) {
        const int* offs = (threadIdx.x >= 2) ? g_offs_frags : g_offs_atoms;
        bounds[threadIdx.x] = offs[g + (threadIdx.x & 1)];
    }
    __syncthreads();

    const int a_start = bounds[0], a_end = bounds[1];
    const int f_start = bounds[2], f_end = bounds[3];

    float4 accA0 = make_float4(0.f, 0.f, 0.f, 0.f);
    float4 accA1 = make_float4(0.f, 0.f, 0.f, 0.f);
    float4 accF  = make_float4(0.f, 0.f, 0.f, 0.f);

    // --- atoms: each warp strides rows by 4, each lane one float4 (512B/row,
    // coalesced LDG.128, L1-bypass via __ldcg since there is zero reuse).
    {
        int r = a_start + warp;
        for (; r + 12 < a_end; r += 16) {
            float4 v0 = __ldcg(reinterpret_cast<const float4*>(x_atoms + (size_t)r * EMB_DIM) + lane);
            float4 v1 = __ldcg(reinterpret_cast<const float4*>(x_atoms + (size_t)(r + 4) * EMB_DIM) + lane);
            float4 v2 = __ldcg(reinterpret_cast<const float4*>(x_atoms + (size_t)(r + 8) * EMB_DIM) + lane);
            float4 v3 = __ldcg(reinterpret_cast<const float4*>(x_atoms + (size_t)(r + 12) * EMB_DIM) + lane);
            acc_add(accA0, v0); acc_add(accA1, v1);
            acc_add(accA0, v2); acc_add(accA1, v3);
        }
        for (; r < a_end; r += 4) {
            float4 v = __ldcg(reinterpret_cast<const float4*>(x_atoms + (size_t)r * EMB_DIM) + lane);
            acc_add(accA0, v);
        }
    }
    // --- frags
    {
        int r = f_start + warp;
        for (; r + 4 < f_end; r += 8) {
            float4 v0 = __ldcg(reinterpret_cast<const float4*>(x_frags + (size_t)r * EMB_DIM) + lane);
            float4 v1 = __ldcg(reinterpret_cast<const float4*>(x_frags + (size_t)(r + 4) * EMB_DIM) + lane);
            acc_add(accF, v0); acc_add(accF, v1);
        }
        if (r < f_end) {
            float4 v = __ldcg(reinterpret_cast<const float4*>(x_frags + (size_t)r * EMB_DIM) + lane);
            acc_add(accF, v);
        }
    }

    acc_add(accA0, accA1);
    shA[warp][lane] = accA0;
    shF[warp][lane] = accF;
    __syncthreads();

    // Single epilogue: warp 0 reduces+writes the atoms half, warp 1 the frags half.
    if (warp < 2) {
        const float4 (*sh)[32] = (warp == 0) ? shA : shF;
        float4 a0 = sh[0][lane], a1 = sh[1][lane], a2 = sh[2][lane], a3 = sh[3][lane];
        float4 s = make_float4(a0.x + a1.x + a2.x + a3.x,
                               a0.y + a1.y + a2.y + a3.y,
                               a0.z + a1.z + a2.z + a3.z,
                               a0.w + a1.w + a2.w + a3.w);
        reinterpret_cast<float4*>(out + (size_t)g * (2 * EMB_DIM) + warp * EMB_DIM)[lane] = s;
    }
}

extern "C" void kernel_launch(void* const* d_in, const int* in_sizes, int n_in,
                              void* d_out, int out_size) {
    const float* x_atoms    = (const float*)d_in[0];
    const float* x_frags    = (const float*)d_in[1];
    const void*  batch      = d_in[2];
    const void*  frag_batch = d_in[3];
    float* out = (float*)d_out;

    const int n_atoms = in_sizes[2];
    const int n_frags = in_sizes[3];

    int* offs_atoms = nullptr;
    int* offs_frags = nullptr;
    cudaGetSymbolAddress((void**)&offs_atoms, g_offs_atoms);
    cudaGetSymbolAddress((void**)&offs_frags, g_offs_frags);

    const int chunks = ((n_atoms + 7) >> 3) + ((n_frags + 7) >> 3);
    const int T = 256;
    build_offsets_fused<<<(chunks + T - 1) / T, T>>>(batch, n_atoms, offs_atoms,
                                                     frag_batch, n_frags, offs_frags);
    fragnet_pool_kernel<<<NUM_GRAPHS, 128>>>(x_atoms, x_frags, out);
}